// round 1
// baseline (speedup 1.0000x reference)
#include <cuda_runtime.h>
#include <cstdint>

// Problem constants
#define B_      8
#define T_      2048
#define C_      1024
#define G_      2
#define E_      320
#define D_      256
#define GE_     640                      // G*E (codes)
#define M_TOT   (B_*T_)                  // 16384 (b,t) rows
#define NROWS   16                       // B*G argmax rows
#define ROW_SPAN 655360u                 // T*E elements per argmax row
#define OUT_ELEMS (B_*T_*G_*D_)          // 16,777,216 floats

// Per-row best (packed: [63:32]=monotone-mapped float, [31:0]=~idx for
// first-occurrence tie-break under max)
__device__ unsigned long long g_best[NROWS];

__device__ __forceinline__ unsigned int float_to_ordered(float f) {
    unsigned int u = __float_as_uint(f);
    return (u & 0x80000000u) ? ~u : (u | 0x80000000u);
}

// ---------------------------------------------------------------------------
// Kernel 1: zero the output + reset the argmax scratch
// ---------------------------------------------------------------------------
__global__ void zero_out_kernel(float4* __restrict__ out) {
    if (blockIdx.x == 0 && threadIdx.x < NROWS) g_best[threadIdx.x] = 0ull;
    unsigned int i = blockIdx.x * blockDim.x + threadIdx.x;
    const unsigned int n4 = OUT_ELEMS / 4;
    if (i < n4) out[i] = make_float4(0.f, 0.f, 0.f, 0.f);
}

// ---------------------------------------------------------------------------
// Kernel 2: fused GEMM (X @ W^T + b) + per-row argmax reduction.
// Tile: 64 rows x 64 codes per block, 256 threads, 4x4 per thread, K step 16.
// All 64 rows of an M-tile share the same argmax row (64 | 1024).
// ---------------------------------------------------------------------------
__global__ void __launch_bounds__(256, 4)
gemm_argmax_kernel(const float* __restrict__ X,
                   const float* __restrict__ W,
                   const float* __restrict__ bias) {
    __shared__ float As[16][64];   // [k][m]
    __shared__ float Bs[16][64];   // [k][n]
    __shared__ unsigned long long sred[256];

    const int m0  = blockIdx.x * 64;
    const int n0  = blockIdx.y * 64;
    const int tid = threadIdx.x;
    const int tx  = tid & 15;      // code group
    const int ty  = tid >> 4;      // row group

    float acc[4][4];
#pragma unroll
    for (int i = 0; i < 4; i++)
#pragma unroll
        for (int j = 0; j < 4; j++) acc[i][j] = 0.f;

    for (int k0 = 0; k0 < C_; k0 += 16) {
#pragma unroll
        for (int i = 0; i < 4; i++) {
            int idx = tid + i * 256;          // 0..1023
            int kk  = idx & 15;
            int r   = idx >> 4;               // 0..63
            As[kk][r] = X[(size_t)(m0 + r) * C_ + k0 + kk];
            Bs[kk][r] = W[(size_t)(n0 + r) * C_ + k0 + kk];
        }
        __syncthreads();

#pragma unroll
        for (int kk = 0; kk < 16; kk++) {
            const float4 a4 = *reinterpret_cast<const float4*>(&As[kk][ty * 4]);
            const float4 b4 = *reinterpret_cast<const float4*>(&Bs[kk][tx * 4]);
            const float a[4] = {a4.x, a4.y, a4.z, a4.w};
            const float b[4] = {b4.x, b4.y, b4.z, b4.w};
#pragma unroll
            for (int i = 0; i < 4; i++)
#pragma unroll
                for (int j = 0; j < 4; j++) acc[i][j] = fmaf(a[i], b[j], acc[i][j]);
        }
        __syncthreads();
    }

    // Bias + thread-local argmax over its 4x4 tile of logits.
    const int r_row = m0 >> 10;               // which of the 16 argmax rows
    unsigned long long best = 0ull;
#pragma unroll
    for (int j = 0; j < 4; j++) {
        const int   n  = n0 + tx * 4 + j;
        const float bb = bias[n];
#pragma unroll
        for (int i = 0; i < 4; i++) {
            const float v  = acc[i][j] + bb;
            const int   gm = m0 + ty * 4 + i;                 // global (b*T+t)
            const unsigned int idx =
                (unsigned int)((unsigned long long)gm * GE_ + n
                               - (unsigned long long)r_row * ROW_SPAN);
            const unsigned long long p =
                ((unsigned long long)float_to_ordered(v) << 32)
                | (unsigned long long)(0xFFFFFFFFu - idx);    // tie -> smaller idx
            best = (p > best) ? p : best;
        }
    }

    // Block reduction then one atomic per block.
    sred[tid] = best;
    __syncthreads();
#pragma unroll
    for (int s = 128; s > 0; s >>= 1) {
        if (tid < s) {
            unsigned long long o = sred[tid + s];
            if (o > sred[tid]) sred[tid] = o;
        }
        __syncthreads();
    }
    if (tid == 0) atomicMax(&g_best[r_row], sred[0]);
}

// ---------------------------------------------------------------------------
// Kernel 3: scatter the 16 winning codebook rows into the (zeroed) output.
// ---------------------------------------------------------------------------
__global__ void scatter_kernel(const float* __restrict__ cb,
                               float* __restrict__ out) {
    const int r = blockIdx.x;                          // 0..15
    const unsigned long long p = g_best[r];
    const unsigned int idx = 0xFFFFFFFFu - (unsigned int)(p & 0xFFFFFFFFull);
    const unsigned long long flat = (unsigned long long)r * ROW_SPAN + idx;
    const unsigned int n   = (unsigned int)(flat / GE_);   // (b*T+t)
    const unsigned int rem = (unsigned int)(flat % GE_);   // g*E + e
    const unsigned int g   = rem / E_;
    out[(size_t)n * (G_ * D_) + g * D_ + threadIdx.x] = cb[(size_t)rem * D_ + threadIdx.x];
}

// ---------------------------------------------------------------------------
extern "C" void kernel_launch(void* const* d_in, const int* in_sizes, int n_in,
                              void* d_out, int out_size) {
    const float* X    = (const float*)d_in[0];   // (8,2048,1024)
    const float* W    = (const float*)d_in[1];   // (640,1024)
    const float* bias = (const float*)d_in[2];   // (640)
    const float* cb   = (const float*)d_in[3];   // (640,256)
    float* out        = (float*)d_out;           // (8,2048,512)

    // 1) zero output + reset scratch
    {
        const int n4 = OUT_ELEMS / 4;
        zero_out_kernel<<<(n4 + 255) / 256, 256>>>((float4*)out);
    }
    // 2) fused GEMM + argmax
    {
        dim3 grid(M_TOT / 64, GE_ / 64);   // 256 x 10
        gemm_argmax_kernel<<<grid, 256>>>(X, W, bias);
    }
    // 3) scatter winners
    scatter_kernel<<<NROWS, D_>>>(cb, out);
}

// round 6
// speedup vs baseline: 6.4536x; 6.4536x over previous
#include <cuda_runtime.h>
#include <cuda_bf16.h>
#include <cstdint>

// ---------------------------------------------------------------- constants
#define B_      8
#define T_      2048
#define C_      1024
#define G_      2
#define E_      320
#define GE_     640
#define D_      256
#define M_TOT   16384
#define NROWS   16
#define ROW_SPAN 655360u
#define OUT_ELEMS (B_*T_*G_*D_)          // 8,388,608  (was wrongly 16,777,216!)
#define LOGITS_N ((size_t)M_TOT * GE_)   // 10,485,760

#define BM 128
#define BN 128
#define BK 32
#define PITCH 40            // bf16 per smem row (32 data + 8 pad) -> 80B
#define NCHUNK (C_/BK)      // 32
#define DELTA 4.0f
#define CAND_CAP 65536

// ---------------------------------------------------------------- scratch
__device__ unsigned long long g_best[NROWS];
__device__ unsigned int       g_approx[NROWS];
__device__ int                g_cand_count;
__device__ unsigned int       g_cand[CAND_CAP];
__device__ __align__(16) __nv_bfloat16 g_Xh[(size_t)M_TOT * C_];
__device__ __align__(16) __nv_bfloat16 g_Wh[(size_t)GE_ * C_];
__device__ float              g_logits[LOGITS_N];

// ---------------------------------------------------------------- helpers
__device__ __forceinline__ unsigned int float_to_ordered(float f) {
    unsigned int u = __float_as_uint(f);
    return (u & 0x80000000u) ? ~u : (u | 0x80000000u);
}
__device__ __forceinline__ float ordered_to_float(unsigned int u) {
    unsigned int v = (u & 0x80000000u) ? (u & 0x7FFFFFFFu) : ~u;
    return __uint_as_float(v);
}
__device__ __forceinline__ uint32_t smem_u32(const void* p) {
    uint32_t a;
    asm("{ .reg .u64 t; cvta.to.shared.u64 t, %1; cvt.u32.u64 %0, t; }"
        : "=r"(a) : "l"(p));
    return a;
}
__device__ __forceinline__ void cp16(void* sptr, const void* gptr) {
    uint32_t s = smem_u32(sptr);
    asm volatile("cp.async.cg.shared.global [%0], [%1], 16;"
                 :: "r"(s), "l"(gptr) : "memory");
}
#define CP_COMMIT() asm volatile("cp.async.commit_group;" ::: "memory")
#define CP_WAIT1()  asm volatile("cp.async.wait_group 1;" ::: "memory")
#define CP_WAIT0()  asm volatile("cp.async.wait_group 0;" ::: "memory")

__device__ __forceinline__ void mma16816(float* d, const uint32_t* a,
                                         uint32_t b0, uint32_t b1) {
    asm volatile(
        "mma.sync.aligned.m16n8k16.row.col.f32.bf16.bf16.f32 "
        "{%0,%1,%2,%3}, {%4,%5,%6,%7}, {%8,%9}, {%0,%1,%2,%3};"
        : "+f"(d[0]), "+f"(d[1]), "+f"(d[2]), "+f"(d[3])
        : "r"(a[0]), "r"(a[1]), "r"(a[2]), "r"(a[3]), "r"(b0), "r"(b1));
}

// ---------------------------------------------------------------- kernel 1
__global__ void zero_out_kernel(float4* __restrict__ out) {
    if (blockIdx.x == 0 && threadIdx.x < NROWS) {
        g_best[threadIdx.x]   = 0ull;
        g_approx[threadIdx.x] = 0u;
        if (threadIdx.x == 0) g_cand_count = 0;
    }
    unsigned int i = blockIdx.x * blockDim.x + threadIdx.x;
    if (i < OUT_ELEMS / 4) out[i] = make_float4(0.f, 0.f, 0.f, 0.f);
}

// ---------------------------------------------------------------- converts
__global__ void convert_X_kernel(const float4* __restrict__ src) {
    unsigned int i = blockIdx.x * blockDim.x + threadIdx.x;   // < 4194304
    float4 v = src[i];
    __nv_bfloat162 h0 = __floats2bfloat162_rn(v.x, v.y);
    __nv_bfloat162 h1 = __floats2bfloat162_rn(v.z, v.w);
    ((uint2*)g_Xh)[i] = make_uint2(*(uint32_t*)&h0, *(uint32_t*)&h1);
}
__global__ void convert_W_kernel(const float4* __restrict__ src) {
    unsigned int i = blockIdx.x * blockDim.x + threadIdx.x;   // < 163840
    float4 v = src[i];
    __nv_bfloat162 h0 = __floats2bfloat162_rn(v.x, v.y);
    __nv_bfloat162 h1 = __floats2bfloat162_rn(v.z, v.w);
    ((uint2*)g_Wh)[i] = make_uint2(*(uint32_t*)&h0, *(uint32_t*)&h1);
}

// ---------------------------------------------------------------- kernel 2
// bf16 HMMA GEMM (cp.async double buffered): logits -> g_logits,
// per-row approx max -> g_approx.
__global__ void gemm_approx_kernel(const float* __restrict__ bias) {
    __shared__ __nv_bfloat16 As[2][BM * PITCH];
    __shared__ __nv_bfloat16 Bs[2][BM * PITCH];

    const int tid  = threadIdx.x;
    const int lane = tid & 31;
    const int w    = tid >> 5;
    const int wm   = w >> 1;          // 0..3
    const int wn   = w & 1;           // 0..1
    const int r4   = lane >> 2;
    const int c4   = lane & 3;

    const int m0 = blockIdx.x * BM;
    const int n0 = blockIdx.y * BN;

    const int rowA = tid >> 2;        // 0..63
    const int gcol = tid & 3;

    float acc[2][8][4];
#pragma unroll
    for (int i = 0; i < 2; i++)
#pragma unroll
        for (int j = 0; j < 8; j++)
#pragma unroll
            for (int k = 0; k < 4; k++) acc[i][j][k] = 0.f;

    // issue chunk 0 and chunk 1
#pragma unroll
    for (int c = 0; c < 2; c++) {
        const int k0 = c * BK;
#pragma unroll
        for (int q = 0; q < 2; q++) {
            const int row = rowA + q * 64;
            cp16(&As[c][row * PITCH + gcol * 8],
                 g_Xh + (size_t)(m0 + row) * C_ + k0 + gcol * 8);
            cp16(&Bs[c][row * PITCH + gcol * 8],
                 g_Wh + (size_t)(n0 + row) * C_ + k0 + gcol * 8);
        }
        CP_COMMIT();
    }

    for (int it = 0; it < NCHUNK; ++it) {
        if (it + 1 < NCHUNK) CP_WAIT1(); else CP_WAIT0();
        __syncthreads();

        const int buf = it & 1;
        const uint32_t* A32 = (const uint32_t*)(&As[buf][0]);
        const uint32_t* B32 = (const uint32_t*)(&Bs[buf][0]);
#pragma unroll
        for (int ks = 0; ks < 2; ++ks) {
            const int cc = ks * 8 + c4;
            uint32_t a[2][4];
#pragma unroll
            for (int mt = 0; mt < 2; ++mt) {
                const int r = wm * 32 + mt * 16 + r4;
                a[mt][0] = A32[r * 20 + cc];
                a[mt][1] = A32[(r + 8) * 20 + cc];
                a[mt][2] = A32[r * 20 + cc + 4];
                a[mt][3] = A32[(r + 8) * 20 + cc + 4];
            }
#pragma unroll
            for (int nt = 0; nt < 8; ++nt) {
                const int rb = wn * 64 + nt * 8 + r4;
                const uint32_t b0 = B32[rb * 20 + cc];
                const uint32_t b1 = B32[rb * 20 + cc + 4];
                mma16816(acc[0][nt], a[0], b0, b1);
                mma16816(acc[1][nt], a[1], b0, b1);
            }
        }
        __syncthreads();

        if (it + 2 < NCHUNK) {
            const int k0 = (it + 2) * BK;
#pragma unroll
            for (int q = 0; q < 2; q++) {
                const int row = rowA + q * 64;
                cp16(&As[buf][row * PITCH + gcol * 8],
                     g_Xh + (size_t)(m0 + row) * C_ + k0 + gcol * 8);
                cp16(&Bs[buf][row * PITCH + gcol * 8],
                     g_Wh + (size_t)(n0 + row) * C_ + k0 + gcol * 8);
            }
            CP_COMMIT();
        }
    }

    // epilogue: bias, store logits, per-row approx max
    float best = -3.4e38f;
    const int mBase = m0 + wm * 32;
    const int nBase = n0 + wn * 64;
#pragma unroll
    for (int nt = 0; nt < 8; ++nt) {
        const int nc = nBase + nt * 8 + c4 * 2;
        const float b0 = bias[nc];
        const float b1 = bias[nc + 1];
#pragma unroll
        for (int mt = 0; mt < 2; ++mt) {
            const int mr = mBase + mt * 16 + r4;
            const float v0 = acc[mt][nt][0] + b0;
            const float v1 = acc[mt][nt][1] + b1;
            const float v2 = acc[mt][nt][2] + b0;
            const float v3 = acc[mt][nt][3] + b1;
            const size_t o0 = (size_t)mr * GE_ + nc;
            const size_t o1 = (size_t)(mr + 8) * GE_ + nc;
            if (o1 + 1 < LOGITS_N) {
                *(float2*)(g_logits + o0) = make_float2(v0, v1);
                *(float2*)(g_logits + o1) = make_float2(v2, v3);
            }
            best = fmaxf(best, fmaxf(fmaxf(v0, v1), fmaxf(v2, v3)));
        }
    }
#pragma unroll
    for (int o = 16; o; o >>= 1)
        best = fmaxf(best, __shfl_xor_sync(0xFFFFFFFFu, best, o));
    if (lane == 0) atomicMax(&g_approx[(m0 >> 10) & (NROWS - 1)],
                             float_to_ordered(best));
}

// ---------------------------------------------------------------- kernel 3
__global__ void scan_kernel() {
    const unsigned int i = blockIdx.x * blockDim.x + threadIdx.x;
    if (i >= (unsigned int)LOGITS_N) return;
    const float v = g_logits[i];
    const unsigned int m = i / GE_;
    const unsigned int r = (m >> 10) & (NROWS - 1);
    const float thr = ordered_to_float(g_approx[r]) - DELTA;
    if (v >= thr) {
        const int pos = atomicAdd(&g_cand_count, 1);
        if (pos >= 0 && pos < CAND_CAP) g_cand[pos] = i;
    }
}

// ---------------------------------------------------------------- kernel 4
__global__ void exact_kernel(const float* __restrict__ X,
                             const float* __restrict__ W,
                             const float* __restrict__ bias) {
    const int lane = threadIdx.x & 31;
    const int wid  = threadIdx.x >> 5;          // 0..3
    int cnt = g_cand_count;
    if (cnt > CAND_CAP) cnt = CAND_CAP;
    for (int ci = blockIdx.x * 4 + wid; ci < cnt; ci += gridDim.x * 4) {
        const unsigned int packed = g_cand[ci];
        if (packed >= (unsigned int)LOGITS_N) continue;
        const unsigned int m = packed / GE_;
        const unsigned int n = packed % GE_;
        const float* xr = X + (size_t)m * C_;
        const float* wr = W + (size_t)n * C_;
        float s = 0.f;
#pragma unroll 8
        for (int j = lane; j < C_; j += 32) s = fmaf(xr[j], wr[j], s);
#pragma unroll
        for (int o = 16; o; o >>= 1) s += __shfl_xor_sync(0xFFFFFFFFu, s, o);
        if (lane == 0) {
            const float ev = s + bias[n];
            const unsigned int r = (m >> 10) & (NROWS - 1);
            const unsigned int idx = (m & 1023u) * (unsigned)GE_ + n;
            const unsigned long long p =
                ((unsigned long long)float_to_ordered(ev) << 32)
                | (unsigned long long)(0xFFFFFFFFu - idx);
            atomicMax(&g_best[r], p);
        }
    }
}

// ---------------------------------------------------------------- kernel 5
__global__ void scatter_kernel(const float* __restrict__ cb,
                               float* __restrict__ out) {
    const int r = blockIdx.x;
    if (r >= NROWS) return;
    const unsigned long long p = g_best[r];
    if (p == 0ull) return;
    const unsigned int idx = 0xFFFFFFFFu - (unsigned int)(p & 0xFFFFFFFFull);
    if (idx >= ROW_SPAN) return;
    const unsigned long long flat = (unsigned long long)r * ROW_SPAN + idx;
    const unsigned int n   = (unsigned int)(flat / GE_);
    const unsigned int rem = (unsigned int)(flat % GE_);
    const unsigned int g   = rem / E_;
    const size_t oidx = (size_t)n * (G_ * D_) + g * D_ + threadIdx.x;
    if (oidx < (size_t)OUT_ELEMS && rem < GE_)
        out[oidx] = cb[(size_t)rem * D_ + threadIdx.x];
}

// ---------------------------------------------------------------- launch
extern "C" void kernel_launch(void* const* d_in, const int* in_sizes, int n_in,
                              void* d_out, int out_size) {
    const float* X    = (const float*)d_in[0];
    const float* W    = (const float*)d_in[1];
    const float* bias = (const float*)d_in[2];
    const float* cb   = (const float*)d_in[3];
    float* out        = (float*)d_out;

    zero_out_kernel<<<OUT_ELEMS / 4 / 256, 256>>>((float4*)out);
    convert_X_kernel<<<(M_TOT * C_ / 4) / 256, 256>>>((const float4*)X);
    convert_W_kernel<<<(GE_ * C_ / 4) / 256, 256>>>((const float4*)W);

    dim3 grid(M_TOT / BM, GE_ / BN);     // 128 x 5
    gemm_approx_kernel<<<grid, 256>>>(bias);

    scan_kernel<<<(unsigned)((LOGITS_N + 1023) / 1024), 1024>>>();
    exact_kernel<<<64, 128>>>(X, W, bias);
    scatter_kernel<<<NROWS, D_>>>(cb, out);
}

// round 7
// speedup vs baseline: 8.4390x; 1.3076x over previous
#include <cuda_runtime.h>
#include <cuda_bf16.h>
#include <cstdint>

// ---------------------------------------------------------------- constants
#define B_      8
#define T_      2048
#define C_      1024
#define G_      2
#define E_      320
#define GE_     640
#define D_      256
#define M_TOT   16384
#define NROWS   16
#define ROW_SPAN 655360u
#define OUT_ELEMS (B_*T_*G_*D_)          // 8,388,608
#define LOGITS_N ((size_t)M_TOT * GE_)   // 10,485,760

#define BM 128
#define BN 128
#define BK 32
#define PITCH 40            // bf16 per smem row (32 data + 8 pad) -> 80B
#define NCHUNK (C_/BK)      // 32
#define NSTAGE 4
#define STAGE_ELE (BM * PITCH)           // 5120 bf16 per operand per stage
#define SMEM_BYTES (NSTAGE * 2 * STAGE_ELE * 2)   // 81920
#define DELTA 4.0f
#define CAND_CAP 65536

// ---------------------------------------------------------------- scratch
__device__ unsigned long long g_best[NROWS];
__device__ int                g_cand_count;
__device__ unsigned int       g_cand[CAND_CAP];
__device__ __align__(16) __nv_bfloat16 g_Xh[(size_t)M_TOT * C_];
__device__ __align__(16) __nv_bfloat16 g_Wh[(size_t)GE_ * C_];

// ---------------------------------------------------------------- helpers
__device__ __forceinline__ unsigned int float_to_ordered(float f) {
    unsigned int u = __float_as_uint(f);
    return (u & 0x80000000u) ? ~u : (u | 0x80000000u);
}
__device__ __forceinline__ uint32_t smem_u32(const void* p) {
    uint32_t a;
    asm("{ .reg .u64 t; cvta.to.shared.u64 t, %1; cvt.u32.u64 %0, t; }"
        : "=r"(a) : "l"(p));
    return a;
}
__device__ __forceinline__ void cp16(void* sptr, const void* gptr) {
    uint32_t s = smem_u32(sptr);
    asm volatile("cp.async.cg.shared.global [%0], [%1], 16;"
                 :: "r"(s), "l"(gptr) : "memory");
}
#define CP_COMMIT() asm volatile("cp.async.commit_group;" ::: "memory")
#define CP_WAIT2()  asm volatile("cp.async.wait_group 2;" ::: "memory")
#define CP_WAIT1()  asm volatile("cp.async.wait_group 1;" ::: "memory")
#define CP_WAIT0()  asm volatile("cp.async.wait_group 0;" ::: "memory")

__device__ __forceinline__ void mma16816(float* d, const uint32_t* a,
                                         uint32_t b0, uint32_t b1) {
    asm volatile(
        "mma.sync.aligned.m16n8k16.row.col.f32.bf16.bf16.f32 "
        "{%0,%1,%2,%3}, {%4,%5,%6,%7}, {%8,%9}, {%0,%1,%2,%3};"
        : "+f"(d[0]), "+f"(d[1]), "+f"(d[2]), "+f"(d[3])
        : "r"(a[0]), "r"(a[1]), "r"(a[2]), "r"(a[3]), "r"(b0), "r"(b1));
}

// ---------------------------------------------------------------- kernel 1
// Fused prep: zero output, convert X and W to bf16, init scalars.
__global__ void prep_kernel(const float4* __restrict__ X4,
                            const float4* __restrict__ W4,
                            float4* __restrict__ out) {
    const unsigned int i = blockIdx.x * blockDim.x + threadIdx.x;
    if (i < NROWS) g_best[i] = 0ull;
    if (i == 0) g_cand_count = 0;
    if (i < OUT_ELEMS / 4) out[i] = make_float4(0.f, 0.f, 0.f, 0.f);
    if (i < (unsigned)(M_TOT * C_ / 4)) {
        float4 v = X4[i];
        __nv_bfloat162 h0 = __floats2bfloat162_rn(v.x, v.y);
        __nv_bfloat162 h1 = __floats2bfloat162_rn(v.z, v.w);
        ((uint2*)g_Xh)[i] = make_uint2(*(uint32_t*)&h0, *(uint32_t*)&h1);
    }
    if (i < (unsigned)(GE_ * C_ / 4)) {
        float4 v = W4[i];
        __nv_bfloat162 h0 = __floats2bfloat162_rn(v.x, v.y);
        __nv_bfloat162 h1 = __floats2bfloat162_rn(v.z, v.w);
        ((uint2*)g_Wh)[i] = make_uint2(*(uint32_t*)&h0, *(uint32_t*)&h1);
    }
}

// ---------------------------------------------------------------- kernel 2
// bf16 HMMA GEMM, 4-stage cp.async pipeline, ONE sync per K-chunk.
// Epilogue: bias + tile max + push candidates within DELTA of tile max.
__global__ void gemm_cand_kernel(const float* __restrict__ bias) {
    extern __shared__ __nv_bfloat16 sm[];
    __nv_bfloat16* As = sm;                         // NSTAGE * 5120
    __nv_bfloat16* Bs = sm + NSTAGE * STAGE_ELE;    // NSTAGE * 5120
    __shared__ float  s_wmax[8];
    __shared__ float  s_tmax;

    const int tid  = threadIdx.x;
    const int lane = tid & 31;
    const int w    = tid >> 5;
    const int wm   = w >> 1;          // 0..3
    const int wn   = w & 1;           // 0..1
    const int r4   = lane >> 2;
    const int c4   = lane & 3;

    const int m0 = blockIdx.x * BM;
    const int n0 = blockIdx.y * BN;

    const int rowA = tid >> 2;        // 0..63
    const int gcol = tid & 3;

    float acc[2][8][4];
#pragma unroll
    for (int i = 0; i < 2; i++)
#pragma unroll
        for (int j = 0; j < 8; j++)
#pragma unroll
            for (int k = 0; k < 4; k++) acc[i][j][k] = 0.f;

    // prologue: stages 0..2
#pragma unroll
    for (int c = 0; c < 3; c++) {
        const int k0 = c * BK;
#pragma unroll
        for (int q = 0; q < 2; q++) {
            const int row = rowA + q * 64;
            cp16(As + c * STAGE_ELE + row * PITCH + gcol * 8,
                 g_Xh + (size_t)(m0 + row) * C_ + k0 + gcol * 8);
            cp16(Bs + c * STAGE_ELE + row * PITCH + gcol * 8,
                 g_Wh + (size_t)(n0 + row) * C_ + k0 + gcol * 8);
        }
        CP_COMMIT();
    }

    for (int it = 0; it < NCHUNK; ++it) {
        if (it < NCHUNK - 2)      CP_WAIT2();
        else if (it == NCHUNK - 2) CP_WAIT1();
        else                       CP_WAIT0();
        __syncthreads();   // publishes chunk `it`; proves chunk it-1 fully consumed

        // refill slot (it+3)%4 == (it-1)%4 (freed last iteration)
        if (it + 3 < NCHUNK) {
            const int slot = (it + 3) & (NSTAGE - 1);
            const int k0 = (it + 3) * BK;
#pragma unroll
            for (int q = 0; q < 2; q++) {
                const int row = rowA + q * 64;
                cp16(As + slot * STAGE_ELE + row * PITCH + gcol * 8,
                     g_Xh + (size_t)(m0 + row) * C_ + k0 + gcol * 8);
                cp16(Bs + slot * STAGE_ELE + row * PITCH + gcol * 8,
                     g_Wh + (size_t)(n0 + row) * C_ + k0 + gcol * 8);
            }
            CP_COMMIT();
        }

        const int buf = it & (NSTAGE - 1);
        const uint32_t* A32 = (const uint32_t*)(As + buf * STAGE_ELE);
        const uint32_t* B32 = (const uint32_t*)(Bs + buf * STAGE_ELE);
#pragma unroll
        for (int ks = 0; ks < 2; ++ks) {
            const int cc = ks * 8 + c4;
            uint32_t a[2][4];
#pragma unroll
            for (int mt = 0; mt < 2; ++mt) {
                const int r = wm * 32 + mt * 16 + r4;
                a[mt][0] = A32[r * 20 + cc];
                a[mt][1] = A32[(r + 8) * 20 + cc];
                a[mt][2] = A32[r * 20 + cc + 4];
                a[mt][3] = A32[(r + 8) * 20 + cc + 4];
            }
#pragma unroll
            for (int nt = 0; nt < 8; ++nt) {
                const int rb = wn * 64 + nt * 8 + r4;
                const uint32_t b0 = B32[rb * 20 + cc];
                const uint32_t b1 = B32[rb * 20 + cc + 4];
                mma16816(acc[0][nt], a[0], b0, b1);
                mma16816(acc[1][nt], a[1], b0, b1);
            }
        }
    }

    // ---------------- epilogue: bias in-place, tile max, candidate push
    float best = -3.4e38f;
    const int mBase = m0 + wm * 32;
    const int nBase = n0 + wn * 64;
#pragma unroll
    for (int nt = 0; nt < 8; ++nt) {
        const int nc = nBase + nt * 8 + c4 * 2;
        const float b0 = bias[nc];
        const float b1 = bias[nc + 1];
#pragma unroll
        for (int mt = 0; mt < 2; ++mt) {
            acc[mt][nt][0] += b0;
            acc[mt][nt][1] += b1;
            acc[mt][nt][2] += b0;
            acc[mt][nt][3] += b1;
            best = fmaxf(best,
                   fmaxf(fmaxf(acc[mt][nt][0], acc[mt][nt][1]),
                         fmaxf(acc[mt][nt][2], acc[mt][nt][3])));
        }
    }
#pragma unroll
    for (int o = 16; o; o >>= 1)
        best = fmaxf(best, __shfl_xor_sync(0xFFFFFFFFu, best, o));
    if (lane == 0) s_wmax[w] = best;
    __syncthreads();
    if (tid == 0) {
        float t = s_wmax[0];
#pragma unroll
        for (int i = 1; i < 8; i++) t = fmaxf(t, s_wmax[i]);
        s_tmax = t;
    }
    __syncthreads();
    const float thr = s_tmax - DELTA;

#pragma unroll
    for (int nt = 0; nt < 8; ++nt) {
        const int nc = nBase + nt * 8 + c4 * 2;
#pragma unroll
        for (int mt = 0; mt < 2; ++mt) {
#pragma unroll
            for (int e = 0; e < 4; ++e) {
                if (acc[mt][nt][e] >= thr) {
                    const int mr = mBase + mt * 16 + r4 + (e >= 2 ? 8 : 0);
                    const int n  = nc + (e & 1);
                    const unsigned int packed =
                        (unsigned int)mr * (unsigned)GE_ + (unsigned)n;
                    const int pos = atomicAdd(&g_cand_count, 1);
                    if (pos >= 0 && pos < CAND_CAP) g_cand[pos] = packed;
                }
            }
        }
    }
}

// ---------------------------------------------------------------- kernel 3
// Exact fp32 dot for every candidate; one warp per candidate.
__global__ void exact_kernel(const float* __restrict__ X,
                             const float* __restrict__ W,
                             const float* __restrict__ bias) {
    const int lane = threadIdx.x & 31;
    const int wid  = threadIdx.x >> 5;          // 0..7
    int cnt = g_cand_count;
    if (cnt > CAND_CAP) cnt = CAND_CAP;
    for (int ci = blockIdx.x * 8 + wid; ci < cnt; ci += gridDim.x * 8) {
        const unsigned int packed = g_cand[ci];
        if (packed >= (unsigned int)LOGITS_N) continue;
        const unsigned int m = packed / GE_;
        const unsigned int n = packed % GE_;
        const float* xr = X + (size_t)m * C_;
        const float* wr = W + (size_t)n * C_;
        float s = 0.f;
#pragma unroll 8
        for (int j = lane; j < C_; j += 32) s = fmaf(xr[j], wr[j], s);
#pragma unroll
        for (int o = 16; o; o >>= 1) s += __shfl_xor_sync(0xFFFFFFFFu, s, o);
        if (lane == 0) {
            const float ev = s + bias[n];
            const unsigned int r = (m >> 10) & (NROWS - 1);
            const unsigned int idx = (m & 1023u) * (unsigned)GE_ + n;
            const unsigned long long p =
                ((unsigned long long)float_to_ordered(ev) << 32)
                | (unsigned long long)(0xFFFFFFFFu - idx);
            atomicMax(&g_best[r], p);
        }
    }
}

// ---------------------------------------------------------------- kernel 4
__global__ void scatter_kernel(const float* __restrict__ cb,
                               float* __restrict__ out) {
    const int r = blockIdx.x;
    if (r >= NROWS) return;
    const unsigned long long p = g_best[r];
    if (p == 0ull) return;
    const unsigned int idx = 0xFFFFFFFFu - (unsigned int)(p & 0xFFFFFFFFull);
    if (idx >= ROW_SPAN) return;
    const unsigned long long flat = (unsigned long long)r * ROW_SPAN + idx;
    const unsigned int n   = (unsigned int)(flat / GE_);
    const unsigned int rem = (unsigned int)(flat % GE_);
    const unsigned int g   = rem / E_;
    const size_t oidx = (size_t)n * (G_ * D_) + g * D_ + threadIdx.x;
    if (oidx < (size_t)OUT_ELEMS && rem < GE_)
        out[oidx] = cb[(size_t)rem * D_ + threadIdx.x];
}

// ---------------------------------------------------------------- launch
extern "C" void kernel_launch(void* const* d_in, const int* in_sizes, int n_in,
                              void* d_out, int out_size) {
    const float* X    = (const float*)d_in[0];
    const float* W    = (const float*)d_in[1];
    const float* bias = (const float*)d_in[2];
    const float* cb   = (const float*)d_in[3];
    float* out        = (float*)d_out;

    cudaFuncSetAttribute(gemm_cand_kernel,
                         cudaFuncAttributeMaxDynamicSharedMemorySize, SMEM_BYTES);

    prep_kernel<<<(M_TOT * C_ / 4) / 256, 256>>>(
        (const float4*)X, (const float4*)W, (float4*)out);

    dim3 grid(M_TOT / BM, GE_ / BN);     // 128 x 5
    gemm_cand_kernel<<<grid, 256, SMEM_BYTES>>>(bias);

    exact_kernel<<<128, 256>>>(X, W, bias);
    scatter_kernel<<<NROWS, D_>>>(cb, out);
}

// round 8
// speedup vs baseline: 8.9971x; 1.0661x over previous
#include <cuda_runtime.h>
#include <cuda_bf16.h>
#include <cstdint>

// ---------------------------------------------------------------- constants
#define B_      8
#define T_      2048
#define C_      1024
#define G_      2
#define E_      320
#define GE_     640
#define D_      256
#define M_TOT   16384
#define NROWS   16
#define ROW_SPAN 655360u
#define OUT_ELEMS (B_*T_*G_*D_)          // 8,388,608
#define LOGITS_N ((size_t)M_TOT * GE_)   // 10,485,760

#define BM 128
#define BN 128
#define BK 32
#define PITCH 40            // bf16 per smem row (32 data + 8 pad) -> 80B
#define NCHUNK (C_/BK)      // 32
#define NSTAGE 4
#define STAGE_ELE (BM * PITCH)           // 5120 bf16 per operand per stage
#define STAGE_BYTES (STAGE_ELE * 2)
#define SMEM_BYTES (NSTAGE * 2 * STAGE_BYTES)     // 81920
#define DELTA 4.0f
#define CAND_CAP 65536

// ---------------------------------------------------------------- scratch
__device__ unsigned long long g_best[NROWS];
__device__ int                g_cand_count;
__device__ unsigned int       g_cand[CAND_CAP];
__device__ __align__(16) __nv_bfloat16 g_Xh[(size_t)M_TOT * C_];
__device__ __align__(16) __nv_bfloat16 g_Wh[(size_t)GE_ * C_];

// ---------------------------------------------------------------- helpers
__device__ __forceinline__ unsigned int float_to_ordered(float f) {
    unsigned int u = __float_as_uint(f);
    return (u & 0x80000000u) ? ~u : (u | 0x80000000u);
}
__device__ __forceinline__ uint32_t smem_u32(const void* p) {
    uint32_t a;
    asm("{ .reg .u64 t; cvta.to.shared.u64 t, %1; cvt.u32.u64 %0, t; }"
        : "=r"(a) : "l"(p));
    return a;
}
__device__ __forceinline__ void cp16(void* sptr, const void* gptr) {
    uint32_t s = smem_u32(sptr);
    asm volatile("cp.async.cg.shared.global [%0], [%1], 16;"
                 :: "r"(s), "l"(gptr) : "memory");
}
#define CP_COMMIT() asm volatile("cp.async.commit_group;" ::: "memory")
#define CP_WAIT2()  asm volatile("cp.async.wait_group 2;" ::: "memory")
#define CP_WAIT1()  asm volatile("cp.async.wait_group 1;" ::: "memory")
#define CP_WAIT0()  asm volatile("cp.async.wait_group 0;" ::: "memory")

__device__ __forceinline__ void mma16816(float* d, const uint32_t* a,
                                         uint32_t b0, uint32_t b1) {
    asm volatile(
        "mma.sync.aligned.m16n8k16.row.col.f32.bf16.bf16.f32 "
        "{%0,%1,%2,%3}, {%4,%5,%6,%7}, {%8,%9}, {%0,%1,%2,%3};"
        : "+f"(d[0]), "+f"(d[1]), "+f"(d[2]), "+f"(d[3])
        : "r"(a[0]), "r"(a[1]), "r"(a[2]), "r"(a[3]), "r"(b0), "r"(b1));
}
__device__ __forceinline__ void ldmx4(uint32_t* r, uint32_t addr) {
    asm volatile(
        "ldmatrix.sync.aligned.m8n8.x4.shared.b16 {%0,%1,%2,%3}, [%4];"
        : "=r"(r[0]), "=r"(r[1]), "=r"(r[2]), "=r"(r[3]) : "r"(addr));
}

// ---------------------------------------------------------------- kernel 1
// Fused prep: zero output, convert X and W to bf16, init scalars.
__global__ void prep_kernel(const float4* __restrict__ X4,
                            const float4* __restrict__ W4,
                            float4* __restrict__ out) {
    const unsigned int i = blockIdx.x * blockDim.x + threadIdx.x;
    if (i < NROWS) g_best[i] = 0ull;
    if (i == 0) g_cand_count = 0;
    if (i < OUT_ELEMS / 4) out[i] = make_float4(0.f, 0.f, 0.f, 0.f);
    if (i < (unsigned)(M_TOT * C_ / 4)) {
        float4 v = X4[i];
        __nv_bfloat162 h0 = __floats2bfloat162_rn(v.x, v.y);
        __nv_bfloat162 h1 = __floats2bfloat162_rn(v.z, v.w);
        ((uint2*)g_Xh)[i] = make_uint2(*(uint32_t*)&h0, *(uint32_t*)&h1);
    }
    if (i < (unsigned)(GE_ * C_ / 4)) {
        float4 v = W4[i];
        __nv_bfloat162 h0 = __floats2bfloat162_rn(v.x, v.y);
        __nv_bfloat162 h1 = __floats2bfloat162_rn(v.z, v.w);
        ((uint2*)g_Wh)[i] = make_uint2(*(uint32_t*)&h0, *(uint32_t*)&h1);
    }
}

// ---------------------------------------------------------------- kernel 2
// bf16 HMMA GEMM, 4-stage cp.async pipeline, ldmatrix fragment loads.
// Epilogue: bias + tile max + push candidates within DELTA of tile max.
__global__ void gemm_cand_kernel(const float* __restrict__ bias) {
    extern __shared__ __nv_bfloat16 sm[];
    __nv_bfloat16* As = sm;                         // NSTAGE * 5120
    __nv_bfloat16* Bs = sm + NSTAGE * STAGE_ELE;    // NSTAGE * 5120
    __shared__ float  s_wmax[8];
    __shared__ float  s_tmax;

    const int tid  = threadIdx.x;
    const int lane = tid & 31;
    const int w    = tid >> 5;
    const int wm   = w >> 1;          // 0..3
    const int wn   = w & 1;           // 0..1
    const int r4   = lane >> 2;
    const int c4   = lane & 3;

    const int m0 = blockIdx.x * BM;
    const int n0 = blockIdx.y * BN;

    const int rowA = tid >> 2;        // 0..63
    const int gcol = tid & 3;

    // ldmatrix per-lane base addresses (bytes)
    const uint32_t smA = smem_u32(As);
    const uint32_t smB = smem_u32(Bs);
    // A x4 tile (16 rows x 16 k): lanes 0-15 -> rows, lanes 16-31 -> k+8
    const uint32_t aAddrBase = smA +
        (((wm * 32 + (lane & 15)) * PITCH + ((lane >> 4) << 3)) << 1);
    // B x4 tile (16 n x 16 k): lanes 0-7 n-lo/k-lo, 8-15 n-lo/k-hi,
    //                          16-23 n-hi/k-lo, 24-31 n-hi/k-hi
    const uint32_t bAddrBase = smB +
        (((wn * 64 + (lane & 7) + ((lane >> 4) << 3)) * PITCH
          + (((lane >> 3) & 1) << 3)) << 1);

    float acc[2][8][4];
#pragma unroll
    for (int i = 0; i < 2; i++)
#pragma unroll
        for (int j = 0; j < 8; j++)
#pragma unroll
            for (int k = 0; k < 4; k++) acc[i][j][k] = 0.f;

    // prologue: stages 0..2
#pragma unroll
    for (int c = 0; c < 3; c++) {
        const int k0 = c * BK;
#pragma unroll
        for (int q = 0; q < 2; q++) {
            const int row = rowA + q * 64;
            cp16(As + c * STAGE_ELE + row * PITCH + gcol * 8,
                 g_Xh + (size_t)(m0 + row) * C_ + k0 + gcol * 8);
            cp16(Bs + c * STAGE_ELE + row * PITCH + gcol * 8,
                 g_Wh + (size_t)(n0 + row) * C_ + k0 + gcol * 8);
        }
        CP_COMMIT();
    }

    for (int it = 0; it < NCHUNK; ++it) {
        if (it < NCHUNK - 2)       CP_WAIT2();
        else if (it == NCHUNK - 2) CP_WAIT1();
        else                       CP_WAIT0();
        __syncthreads();   // publishes chunk `it`; proves it-1 fully consumed

        if (it + 3 < NCHUNK) {
            const int slot = (it + 3) & (NSTAGE - 1);
            const int k0 = (it + 3) * BK;
#pragma unroll
            for (int q = 0; q < 2; q++) {
                const int row = rowA + q * 64;
                cp16(As + slot * STAGE_ELE + row * PITCH + gcol * 8,
                     g_Xh + (size_t)(m0 + row) * C_ + k0 + gcol * 8);
                cp16(Bs + slot * STAGE_ELE + row * PITCH + gcol * 8,
                     g_Wh + (size_t)(n0 + row) * C_ + k0 + gcol * 8);
            }
            CP_COMMIT();
        }

        const uint32_t stageOff = (uint32_t)(it & (NSTAGE - 1)) * STAGE_BYTES;
        const uint32_t aAddr = aAddrBase + stageOff;
        const uint32_t bAddr = bAddrBase + stageOff;
#pragma unroll
        for (int ks = 0; ks < 2; ++ks) {
            const uint32_t kOffB = (uint32_t)(ks * 16 * 2);   // 16 k elems
            uint32_t a0[4], a1[4];
            ldmx4(a0, aAddr + kOffB);                          // mt = 0
            ldmx4(a1, aAddr + 16 * PITCH * 2 + kOffB);         // mt = 1
#pragma unroll
            for (int nt2 = 0; nt2 < 4; ++nt2) {
                uint32_t bb[4];
                ldmx4(bb, bAddr + (uint32_t)(nt2 * 16 * PITCH * 2) + kOffB);
                mma16816(acc[0][2 * nt2],     a0, bb[0], bb[1]);
                mma16816(acc[0][2 * nt2 + 1], a0, bb[2], bb[3]);
                mma16816(acc[1][2 * nt2],     a1, bb[0], bb[1]);
                mma16816(acc[1][2 * nt2 + 1], a1, bb[2], bb[3]);
            }
        }
    }

    // ---------------- epilogue: bias in-place, tile max, candidate push
    float best = -3.4e38f;
    const int mBase = m0 + wm * 32;
    const int nBase = n0 + wn * 64;
#pragma unroll
    for (int nt = 0; nt < 8; ++nt) {
        const int nc = nBase + nt * 8 + c4 * 2;
        const float b0 = bias[nc];
        const float b1 = bias[nc + 1];
#pragma unroll
        for (int mt = 0; mt < 2; ++mt) {
            acc[mt][nt][0] += b0;
            acc[mt][nt][1] += b1;
            acc[mt][nt][2] += b0;
            acc[mt][nt][3] += b1;
            best = fmaxf(best,
                   fmaxf(fmaxf(acc[mt][nt][0], acc[mt][nt][1]),
                         fmaxf(acc[mt][nt][2], acc[mt][nt][3])));
        }
    }
#pragma unroll
    for (int o = 16; o; o >>= 1)
        best = fmaxf(best, __shfl_xor_sync(0xFFFFFFFFu, best, o));
    if (lane == 0) s_wmax[w] = best;
    __syncthreads();
    if (tid == 0) {
        float t = s_wmax[0];
#pragma unroll
        for (int i = 1; i < 8; i++) t = fmaxf(t, s_wmax[i]);
        s_tmax = t;
    }
    __syncthreads();
    const float thr = s_tmax - DELTA;

#pragma unroll
    for (int nt = 0; nt < 8; ++nt) {
        const int nc = nBase + nt * 8 + c4 * 2;
#pragma unroll
        for (int mt = 0; mt < 2; ++mt) {
#pragma unroll
            for (int e = 0; e < 4; ++e) {
                if (acc[mt][nt][e] >= thr) {
                    const int mr = mBase + mt * 16 + r4 + (e >= 2 ? 8 : 0);
                    const int n  = nc + (e & 1);
                    const unsigned int packed =
                        (unsigned int)mr * (unsigned)GE_ + (unsigned)n;
                    const int pos = atomicAdd(&g_cand_count, 1);
                    if (pos >= 0 && pos < CAND_CAP) g_cand[pos] = packed;
                }
            }
        }
    }
}

// ---------------------------------------------------------------- kernel 3
__global__ void exact_kernel(const float* __restrict__ X,
                             const float* __restrict__ W,
                             const float* __restrict__ bias) {
    const int lane = threadIdx.x & 31;
    const int wid  = threadIdx.x >> 5;          // 0..7
    int cnt = g_cand_count;
    if (cnt > CAND_CAP) cnt = CAND_CAP;
    for (int ci = blockIdx.x * 8 + wid; ci < cnt; ci += gridDim.x * 8) {
        const unsigned int packed = g_cand[ci];
        if (packed >= (unsigned int)LOGITS_N) continue;
        const unsigned int m = packed / GE_;
        const unsigned int n = packed % GE_;
        const float* xr = X + (size_t)m * C_;
        const float* wr = W + (size_t)n * C_;
        float s = 0.f;
#pragma unroll 8
        for (int j = lane; j < C_; j += 32) s = fmaf(xr[j], wr[j], s);
#pragma unroll
        for (int o = 16; o; o >>= 1) s += __shfl_xor_sync(0xFFFFFFFFu, s, o);
        if (lane == 0) {
            const float ev = s + bias[n];
            const unsigned int r = (m >> 10) & (NROWS - 1);
            const unsigned int idx = (m & 1023u) * (unsigned)GE_ + n;
            const unsigned long long p =
                ((unsigned long long)float_to_ordered(ev) << 32)
                | (unsigned long long)(0xFFFFFFFFu - idx);
            atomicMax(&g_best[r], p);
        }
    }
}

// ---------------------------------------------------------------- kernel 4
__global__ void scatter_kernel(const float* __restrict__ cb,
                               float* __restrict__ out) {
    const int r = blockIdx.x;
    if (r >= NROWS) return;
    const unsigned long long p = g_best[r];
    if (p == 0ull) return;
    const unsigned int idx = 0xFFFFFFFFu - (unsigned int)(p & 0xFFFFFFFFull);
    if (idx >= ROW_SPAN) return;
    const unsigned long long flat = (unsigned long long)r * ROW_SPAN + idx;
    const unsigned int n   = (unsigned int)(flat / GE_);
    const unsigned int rem = (unsigned int)(flat % GE_);
    const unsigned int g   = rem / E_;
    const size_t oidx = (size_t)n * (G_ * D_) + g * D_ + threadIdx.x;
    if (oidx < (size_t)OUT_ELEMS && rem < GE_)
        out[oidx] = cb[(size_t)rem * D_ + threadIdx.x];
}

// ---------------------------------------------------------------- launch
extern "C" void kernel_launch(void* const* d_in, const int* in_sizes, int n_in,
                              void* d_out, int out_size) {
    const float* X    = (const float*)d_in[0];
    const float* W    = (const float*)d_in[1];
    const float* bias = (const float*)d_in[2];
    const float* cb   = (const float*)d_in[3];
    float* out        = (float*)d_out;

    cudaFuncSetAttribute(gemm_cand_kernel,
                         cudaFuncAttributeMaxDynamicSharedMemorySize, SMEM_BYTES);

    prep_kernel<<<(M_TOT * C_ / 4) / 256, 256>>>(
        (const float4*)X, (const float4*)W, (float4*)out);

    dim3 grid(M_TOT / BM, GE_ / BN);     // 128 x 5
    gemm_cand_kernel<<<grid, 256, SMEM_BYTES>>>(bias);

    exact_kernel<<<128, 256>>>(X, W, bias);
    scatter_kernel<<<NROWS, D_>>>(cb, out);
}